// round 2
// baseline (speedup 1.0000x reference)
#include <cuda_runtime.h>
#include <math.h>

#define QN 4096
#define LN 1024
#define BN 2
#define HDN 256
#define INN 128
#define TOPK 128

// ---------------- scratch (device globals; no allocation) ----------------
__device__ float g_kfull[BN*LN*INN];
__device__ float g_vfull[BN*LN*INN];
__device__ float g_q[QN*INN];
__device__ float g_h0[QN*HDN];
__device__ float g_h1[QN*HDN];
__device__ float g_o[BN*QN*INN];
__device__ float g_mod[BN*QN*HDN];
__device__ float g_m0[BN*QN*HDN];
__device__ float g_m1[BN*QN*HDN];
__device__ float g_hv1[BN*QN*HDN];

// ---------------- K1: kv = tokens @ kv_W ; split into k_full / v_full ----
__global__ __launch_bounds__(256) void k_kv(const float* __restrict__ tokens,
                                            const float* __restrict__ kv_W) {
    __shared__ float a[8][256];
    int tid = threadIdx.x;
    int r0 = blockIdx.x * 8;                 // 256 blocks, rows = b*L+l
    for (int i = tid; i < 8 * 256; i += 256)
        a[i >> 8][i & 255] = tokens[r0 * 256 + i];
    __syncthreads();
    float acc[8];
#pragma unroll
    for (int r = 0; r < 8; r++) acc[r] = 0.f;
#pragma unroll 4
    for (int h = 0; h < 256; h++) {
        float w = kv_W[h * 256 + tid];
#pragma unroll
        for (int r = 0; r < 8; r++) acc[r] = fmaf(a[r][h], w, acc[r]);
    }
#pragma unroll
    for (int r = 0; r < 8; r++) {
        int row = r0 + r;
        if (tid < 128) g_kfull[row * 128 + tid] = acc[r];
        else           g_vfull[row * 128 + tid - 128] = acc[r];
    }
}

// ---------------- K2: gammas, x_q, q, h0, h1 per query ----------------
__global__ __launch_bounds__(256) void k_feat(const float* __restrict__ x,
                                              const float* __restrict__ query_W,
                                              const float* __restrict__ query_b,
                                              const float* __restrict__ q_W,
                                              const float* __restrict__ band_W,
                                              const float* __restrict__ band_b) {
    __shared__ float sg[16][4];
    __shared__ float om0[8], om1[8];
    __shared__ float gq[16][64];
    __shared__ float g1s[16][64];
    __shared__ float xq[16][256];
    int tid = threadIdx.x;
    int q0 = blockIdx.x * 16;                 // 256 blocks
    if (tid < 8) {
        // emulate jnp.logspace: fp32 linspace of exponents, then 10^x
        const float stop0 = (float)2.1072099696478683;   // log10(128)
        float e0 = 1.0f + (float)tid * ((stop0 - 1.0f) / 7.0f);
        om0[tid] = (float)exp10((double)e0);
        const float stop1 = (float)1.5051499783199061;   // log10(32)
        float e1 = 1.0f + (float)tid * ((stop1 - 1.0f) / 7.0f);
        om1[tid] = (float)exp10((double)e1);
    }
    if (tid < 64) sg[tid >> 2][tid & 3] = x[(q0 + (tid >> 2)) * 4 + (tid & 3)];
    __syncthreads();
    for (int i = tid; i < 16 * 64; i += 256) {
        int r = i >> 6, f = i & 63;
        int d = f >> 4, j = f & 15;
        float pg = (float)M_PI * sg[r][d];
        int jj = (j < 8) ? j : j - 8;
        float a0 = pg * om0[jj];
        float a1 = pg * om1[jj];
        gq[r][f]  = (j < 8) ? sinf(a0) : cosf(a0);
        g1s[r][f] = (j < 8) ? sinf(a1) : cosf(a1);
    }
    __syncthreads();
    float accx[16], acc0[16], acc1[16];
#pragma unroll
    for (int r = 0; r < 16; r++) { accx[r] = 0.f; acc0[r] = 0.f; acc1[r] = 0.f; }
    for (int f = 0; f < 64; f++) {
        float wq = query_W[f * 256 + tid];
        float w0 = band_W[f * 256 + tid];
        float w1 = band_W[64 * 256 + f * 256 + tid];
#pragma unroll
        for (int r = 0; r < 16; r++) {
            float gv = gq[r][f];
            accx[r] = fmaf(gv, wq, accx[r]);
            acc0[r] = fmaf(gv, w0, acc0[r]);
            acc1[r] = fmaf(g1s[r][f], w1, acc1[r]);
        }
    }
    float qb = query_b[tid], b0 = band_b[tid], b1 = band_b[256 + tid];
#pragma unroll
    for (int r = 0; r < 16; r++) {
        float xv = fmaxf(accx[r] + qb, 0.f);
        xq[r][tid] = xv;
        g_h0[(q0 + r) * 256 + tid] = fmaxf(acc0[r] + b0, 0.f);
        g_h1[(q0 + r) * 256 + tid] = fmaxf(acc1[r] + b1, 0.f);
    }
    __syncthreads();
    // q = x_q @ q_W  (256 x 128), shared across batches
    int c  = tid & 127;
    int rh = tid >> 7;   // 0/1: rows [0..7] / [8..15]
    float accq[8];
#pragma unroll
    for (int r = 0; r < 8; r++) accq[r] = 0.f;
    for (int h = 0; h < 256; h++) {
        float w = q_W[h * 128 + c];
#pragma unroll
        for (int r = 0; r < 8; r++) accq[r] = fmaf(xq[rh * 8 + r][h], w, accq[r]);
    }
#pragma unroll
    for (int r = 0; r < 8; r++) g_q[(q0 + rh * 8 + r) * 128 + c] = accq[r];
}

// ---------------- K3: windowed sparse attention (both batches) ----------
__global__ __launch_bounds__(256) void k_attn(const float* __restrict__ x,
                                              const int* gDp, const int* gHp,
                                              const int* gWp, const int* gTp) {
    __shared__ __align__(16) float qs[128];
    __shared__ float ps[2][128];
    __shared__ float dnm[2];
    __shared__ float op[2][128];
    int tid = threadIdx.x;
    int q = blockIdx.x;
    if (tid < 128) qs[tid] = g_q[q * 128 + tid];

    // ---- window selection: exact integer emulation of top_k(-bias) ----
    int gD = *gDp, gH = *gHp, gW = *gWp, gT = *gTp;
    float x0 = x[q * 4 + 0], x1 = x[q * 4 + 1], x2 = x[q * 4 + 2], x3 = x[q * 4 + 3];
    int zi = (int)(x0 * (float)gD);
    int yi = (int)(x1 * (float)gH);
    int xi = (int)(x2 * (float)gW);
    int ti = (int)(x3 * (float)gT);
    int idx = ((ti * gD + zi) * gH + yi) * gW + xi;
    long long Ntot = (long long)gD * gH * gW * gT;
    long long a2 = 2LL * idx * LN;           // dist(l) = |a2 - (2l+1)*Ntot|
    int lc = (int)((a2 / Ntot - 1) / 2);
    if (lc < 0) lc = 0;
    if (lc > LN - 1) lc = LN - 1;
    int best = 0; long long bd = 0x7fffffffffffffffLL;
    for (int dl = -2; dl <= 2; dl++) {
        int l = lc + dl;
        if (l < 0 || l >= LN) continue;
        long long d = llabs(a2 - (2LL * l + 1) * Ntot);
        if (d < bd) { bd = d; best = l; }    // ascending scan: tie -> lower l
    }
    int s = best, e = best;
    for (int i = 1; i < TOPK; i++) {
        long long dl2 = (s > 0)      ? llabs(a2 - (2LL * (s - 1) + 1) * Ntot) : 0x7fffffffffffffffLL;
        long long dr2 = (e < LN - 1) ? llabs(a2 - (2LL * (e + 1) + 1) * Ntot) : 0x7fffffffffffffffLL;
        if (dl2 <= dr2) s--; else e++;       // tie -> lower index (left)
    }
    __syncthreads();

    int lane = tid & 31;
    int warp = tid >> 5;
    for (int b = 0; b < BN; b++) {
        // sim: warp-cooperative dot; coalesced float4 K reads
        const float* kb = g_kfull + b * LN * 128;
        const float4 q4 = *reinterpret_cast<const float4*>(qs + lane * 4);
#pragma unroll
        for (int kk = 0; kk < 16; kk++) {
            int k = warp * 16 + kk;
            int l = s + k;
            const float4 k4 = *reinterpret_cast<const float4*>(kb + l * 128 + lane * 4);
            float part = k4.x * q4.x + k4.y * q4.y + k4.z * q4.z + k4.w * q4.w;
            part += __shfl_xor_sync(0xffffffffu, part, 1);
            part += __shfl_xor_sync(0xffffffffu, part, 2);
            part += __shfl_xor_sync(0xffffffffu, part, 4);
            part += __shfl_xor_sync(0xffffffffu, part, 8);
            if ((lane & 15) == 0) ps[lane >> 4][k] = part * 0.125f;
        }
        __syncthreads();
        // softmax (warp 0 -> head 0, warp 1 -> head 1)
        if (tid < 64) {
            int h = warp;
            float v[4];
            float mx = -3.4e38f;
#pragma unroll
            for (int j2 = 0; j2 < 4; j2++) { v[j2] = ps[h][lane + 32 * j2]; mx = fmaxf(mx, v[j2]); }
#pragma unroll
            for (int o2 = 16; o2 > 0; o2 >>= 1) mx = fmaxf(mx, __shfl_xor_sync(0xffffffffu, mx, o2));
            float sum = 0.f;
#pragma unroll
            for (int j2 = 0; j2 < 4; j2++) {
                float ev = expf(v[j2] - mx);
                ps[h][lane + 32 * j2] = ev;
                sum += ev;
            }
#pragma unroll
            for (int o2 = 16; o2 > 0; o2 >>= 1) sum += __shfl_xor_sync(0xffffffffu, sum, o2);
            if (lane == 0) dnm[h] = sum;
        }
        __syncthreads();
        // o: thread-per-output-dim, coalesced V reads; keys split in halves
        {
            int j = tid & 127;
            int half = tid >> 7;
            int h = j >> 6;
            const float* vb = g_vfull + b * LN * 128;
            float acc = 0.f;
#pragma unroll 8
            for (int kk = 0; kk < 64; kk++) {
                int k = half * 64 + kk;
                acc = fmaf(ps[h][k], vb[(s + k) * 128 + j], acc);
            }
            op[half][j] = acc;
        }
        __syncthreads();
        if (tid < 128) {
            float val = (op[0][tid] + op[1][tid]) / dnm[tid >> 6];
            g_o[(b * QN + q) * 128 + tid] = val;
        }
        __syncthreads();
    }
}

// ---------------- K4: modulation = o @ out_W + out_b --------------------
__global__ __launch_bounds__(256) void k_modl(const float* __restrict__ out_W,
                                              const float* __restrict__ out_b) {
    __shared__ float a[16][128];
    int tid = threadIdx.x;
    int r0 = blockIdx.x * 16;                 // 512 blocks
    for (int i = tid; i < 16 * 128; i += 256)
        a[i >> 7][i & 127] = g_o[r0 * 128 + i];
    __syncthreads();
    float acc[16];
#pragma unroll
    for (int r = 0; r < 16; r++) acc[r] = 0.f;
    for (int h = 0; h < 128; h++) {
        float w = out_W[h * 256 + tid];
#pragma unroll
        for (int r = 0; r < 16; r++) acc[r] = fmaf(a[r][h], w, acc[r]);
    }
    float bb = out_b[tid];
#pragma unroll
    for (int r = 0; r < 16; r++) g_mod[(r0 + r) * 256 + tid] = acc[r] + bb;
}

// ---------------- K5: generic 256->256 layer ----------------------------
// mode 0: m0 = relu(h0[q] + mod @ W + b)
// mode 1: m1 = relu(h1[q] + mod @ W + b)
// mode 2: hv1 = relu((m0+m1) @ W + b)
__global__ __launch_bounds__(256) void k_layer(const float* __restrict__ W,
                                               const float* __restrict__ bias,
                                               int mode) {
    const float* X; const float* X2 = nullptr; const float* hadd = nullptr; float* OUT;
    if (mode == 0)      { X = g_mod; hadd = g_h0; OUT = g_m0; }
    else if (mode == 1) { X = g_mod; hadd = g_h1; OUT = g_m1; }
    else                { X = g_m0; X2 = g_m1;   OUT = g_hv1; }
    __shared__ float a[16][256];
    int tid = threadIdx.x;
    int r0 = blockIdx.x * 16;                 // 512 blocks
    for (int i = tid; i < 16 * 256; i += 256) {
        float v = X[r0 * 256 + i];
        if (X2) v += X2[r0 * 256 + i];
        a[i >> 8][i & 255] = v;
    }
    __syncthreads();
    float acc[16];
#pragma unroll
    for (int r = 0; r < 16; r++) acc[r] = 0.f;
    for (int h = 0; h < 256; h++) {
        float w = W[h * 256 + tid];
#pragma unroll
        for (int r = 0; r < 16; r++) acc[r] = fmaf(a[r][h], w, acc[r]);
    }
    float bb = bias[tid];
#pragma unroll
    for (int r = 0; r < 16; r++) {
        float v = acc[r] + bb;
        if (hadd) v += hadd[((r0 + r) & (QN - 1)) * 256 + tid];
        OUT[(r0 + r) * 256 + tid] = fmaxf(v, 0.f);
    }
}

// ---------------- K7: out = m0 . outlW0 + hv1 . outlW1 + biases ---------
__global__ __launch_bounds__(256) void k_out(const float* __restrict__ outl_W,
                                             const float* __restrict__ outl_b,
                                             float* __restrict__ out) {
    int tid = threadIdx.x;
    int r = blockIdx.x * 8 + (tid >> 5);      // 1024 blocks x 8 warps
    int lane = tid & 31;
    float acc = 0.f;
#pragma unroll
    for (int j = 0; j < 8; j++) {
        int c = lane + 32 * j;
        acc = fmaf(g_m0[r * 256 + c],  outl_W[c],       acc);
        acc = fmaf(g_hv1[r * 256 + c], outl_W[256 + c], acc);
    }
#pragma unroll
    for (int o2 = 16; o2 > 0; o2 >>= 1) acc += __shfl_xor_sync(0xffffffffu, acc, o2);
    if (lane == 0) out[r] = acc + outl_b[0] + outl_b[1];
}

// ---------------- launch ------------------------------------------------
extern "C" void kernel_launch(void* const* d_in, const int* in_sizes, int n_in,
                              void* d_out, int out_size) {
    const float* x       = (const float*)d_in[0];
    const float* tokens  = (const float*)d_in[1];
    const float* query_W = (const float*)d_in[2];
    const float* query_b = (const float*)d_in[3];
    const float* q_W     = (const float*)d_in[4];
    const float* kv_W    = (const float*)d_in[5];
    const float* out_W   = (const float*)d_in[6];
    const float* out_b   = (const float*)d_in[7];
    const float* band_W  = (const float*)d_in[8];
    const float* band_b  = (const float*)d_in[9];
    const float* mod_W   = (const float*)d_in[10];
    const float* mod_b   = (const float*)d_in[11];
    const float* hv_W    = (const float*)d_in[12];
    const float* hv_b    = (const float*)d_in[13];
    const float* outl_W  = (const float*)d_in[14];
    const float* outl_b  = (const float*)d_in[15];
    const int*   gD      = (const int*)d_in[16];
    const int*   gH      = (const int*)d_in[17];
    const int*   gW      = (const int*)d_in[18];
    const int*   gT      = (const int*)d_in[19];
    float* out = (float*)d_out;

    k_kv  <<<BN * LN / 8, 256>>>(tokens, kv_W);
    k_feat<<<QN / 16,     256>>>(x, query_W, query_b, q_W, band_W, band_b);
    k_attn<<<QN,          256>>>(x, gD, gH, gW, gT);
    k_modl<<<BN * QN / 16, 256>>>(out_W, out_b);
    k_layer<<<BN * QN / 16, 256>>>(mod_W,            mod_b,       0);
    k_layer<<<BN * QN / 16, 256>>>(mod_W + 256 * 256, mod_b + 256, 1);
    k_layer<<<BN * QN / 16, 256>>>(hv_W,             hv_b,        2);
    k_out <<<BN * QN / 8,  256>>>(outl_W, outl_b, out);
}

// round 3
// speedup vs baseline: 2.4823x; 2.4823x over previous
#include <cuda_runtime.h>
#include <math.h>

#define QN 4096
#define LN 1024
#define BN 2
#define HDN 256
#define INN 128
#define TOPK 128

// ---------------- scratch (device globals; no allocation) ----------------
__device__ float g_kfull[BN*LN*INN];
__device__ float g_vfull[BN*LN*INN];
__device__ float g_q[QN*INN];
__device__ float g_h0[QN*HDN];
__device__ float g_h1[QN*HDN];
__device__ float g_o[BN*QN*INN];
__device__ float g_mod[BN*QN*HDN];
__device__ float g_m0[BN*QN*HDN];
__device__ float g_m1[BN*QN*HDN];
__device__ float g_hv1[BN*QN*HDN];

// ---------------- generic register-blocked GEMM:  OUT[R x 256] ----------
// Block: 32 rows x 256 cols. Thread: 8 rows x 4 cols. K chunked by 64.
// MODE 0: kv split (no bias/relu), OUT=k_full, OUT2=v_full
// MODE 1: out = X@W + b
// MODE 2: out = relu(hadd[row&4095] + X@W + b)
// MODE 3: out = relu((X+X2)@W + b)
template<int KDIM, int MODE>
__global__ __launch_bounds__(256) void k_gemm(const float* __restrict__ X,
                                              const float* __restrict__ X2,
                                              const float* __restrict__ W,
                                              const float* __restrict__ bias,
                                              const float* __restrict__ hadd,
                                              float* __restrict__ OUT,
                                              float* __restrict__ OUT2) {
    __shared__ float a[32][64];
    int tid = threadIdx.x;
    int r0 = blockIdx.x * 32;
    int rg = tid >> 6;           // 4 row groups of 8 rows
    int c0 = (tid & 63) * 4;     // 64 col groups of 4 cols
    float acc[8][4];
#pragma unroll
    for (int r = 0; r < 8; r++)
#pragma unroll
        for (int j = 0; j < 4; j++) acc[r][j] = 0.f;

    for (int kc = 0; kc < KDIM; kc += 64) {
        // stage A chunk [32 rows][64 k] into shared (float4 coalesced)
        for (int i = tid; i < 32 * 16; i += 256) {
            int r = i >> 4, f = (i & 15) * 4;
            const float* p = X + (long long)(r0 + r) * KDIM + kc + f;
            float4 v = *reinterpret_cast<const float4*>(p);
            if (MODE == 3) {
                const float* p2 = X2 + (long long)(r0 + r) * KDIM + kc + f;
                float4 v2 = *reinterpret_cast<const float4*>(p2);
                v.x += v2.x; v.y += v2.y; v.z += v2.z; v.w += v2.w;
            }
            *reinterpret_cast<float4*>(&a[r][f]) = v;
        }
        __syncthreads();
#pragma unroll 8
        for (int k = 0; k < 64; k++) {
            float4 w4 = *reinterpret_cast<const float4*>(W + (kc + k) * 256 + c0);
#pragma unroll
            for (int r = 0; r < 8; r++) {
                float av = a[rg * 8 + r][k];
                acc[r][0] = fmaf(av, w4.x, acc[r][0]);
                acc[r][1] = fmaf(av, w4.y, acc[r][1]);
                acc[r][2] = fmaf(av, w4.z, acc[r][2]);
                acc[r][3] = fmaf(av, w4.w, acc[r][3]);
            }
        }
        __syncthreads();
    }

    float4 bb = make_float4(0.f, 0.f, 0.f, 0.f);
    if (MODE != 0) bb = *reinterpret_cast<const float4*>(bias + c0);
#pragma unroll
    for (int r = 0; r < 8; r++) {
        int row = r0 + rg * 8 + r;
        float4 v;
        v.x = acc[r][0] + bb.x; v.y = acc[r][1] + bb.y;
        v.z = acc[r][2] + bb.z; v.w = acc[r][3] + bb.w;
        if (MODE == 2) {
            const float* hp = hadd + (long long)(row & (QN - 1)) * 256 + c0;
            float4 h4 = *reinterpret_cast<const float4*>(hp);
            v.x += h4.x; v.y += h4.y; v.z += h4.z; v.w += h4.w;
        }
        if (MODE >= 2) {
            v.x = fmaxf(v.x, 0.f); v.y = fmaxf(v.y, 0.f);
            v.z = fmaxf(v.z, 0.f); v.w = fmaxf(v.w, 0.f);
        }
        if (MODE == 0) {
            if (c0 < 128)
                *reinterpret_cast<float4*>(OUT + (long long)row * 128 + c0) = v;
            else
                *reinterpret_cast<float4*>(OUT2 + (long long)row * 128 + c0 - 128) = v;
        } else {
            *reinterpret_cast<float4*>(OUT + (long long)row * 256 + c0) = v;
        }
    }
}

// ---------------- K2: gammas, x_q, q, h0, h1 per query ----------------
__global__ __launch_bounds__(256) void k_feat(const float* __restrict__ x,
                                              const float* __restrict__ query_W,
                                              const float* __restrict__ query_b,
                                              const float* __restrict__ q_W,
                                              const float* __restrict__ band_W,
                                              const float* __restrict__ band_b) {
    __shared__ float sg[16][4];
    __shared__ float om0[8], om1[8];
    __shared__ float gq[16][64];
    __shared__ float g1s[16][64];
    __shared__ float xq[16][256];
    int tid = threadIdx.x;
    int q0 = blockIdx.x * 16;                 // 256 blocks
    if (tid < 8) {
        const float stop0 = (float)2.1072099696478683;   // log10(128)
        float e0 = 1.0f + (float)tid * ((stop0 - 1.0f) / 7.0f);
        om0[tid] = (float)exp10((double)e0);
        const float stop1 = (float)1.5051499783199061;   // log10(32)
        float e1 = 1.0f + (float)tid * ((stop1 - 1.0f) / 7.0f);
        om1[tid] = (float)exp10((double)e1);
    }
    if (tid < 64) sg[tid >> 2][tid & 3] = x[(q0 + (tid >> 2)) * 4 + (tid & 3)];
    __syncthreads();
    for (int i = tid; i < 16 * 64; i += 256) {
        int r = i >> 6, f = i & 63;
        int d = f >> 4, j = f & 15;
        float pg = (float)M_PI * sg[r][d];
        int jj = (j < 8) ? j : j - 8;
        float a0 = pg * om0[jj];
        float a1 = pg * om1[jj];
        gq[r][f]  = (j < 8) ? sinf(a0) : cosf(a0);
        g1s[r][f] = (j < 8) ? sinf(a1) : cosf(a1);
    }
    __syncthreads();
    float accx[16], acc0[16], acc1[16];
#pragma unroll
    for (int r = 0; r < 16; r++) { accx[r] = 0.f; acc0[r] = 0.f; acc1[r] = 0.f; }
    for (int f = 0; f < 64; f++) {
        float wq = query_W[f * 256 + tid];
        float w0 = band_W[f * 256 + tid];
        float w1 = band_W[64 * 256 + f * 256 + tid];
#pragma unroll
        for (int r = 0; r < 16; r++) {
            float gv = gq[r][f];
            accx[r] = fmaf(gv, wq, accx[r]);
            acc0[r] = fmaf(gv, w0, acc0[r]);
            acc1[r] = fmaf(g1s[r][f], w1, acc1[r]);
        }
    }
    float qb = query_b[tid], b0 = band_b[tid], b1 = band_b[256 + tid];
#pragma unroll
    for (int r = 0; r < 16; r++) {
        float xv = fmaxf(accx[r] + qb, 0.f);
        xq[r][tid] = xv;
        g_h0[(q0 + r) * 256 + tid] = fmaxf(acc0[r] + b0, 0.f);
        g_h1[(q0 + r) * 256 + tid] = fmaxf(acc1[r] + b1, 0.f);
    }
    __syncthreads();
    int c  = tid & 127;
    int rh = tid >> 7;
    float accq[8];
#pragma unroll
    for (int r = 0; r < 8; r++) accq[r] = 0.f;
    for (int h = 0; h < 256; h++) {
        float w = q_W[h * 128 + c];
#pragma unroll
        for (int r = 0; r < 8; r++) accq[r] = fmaf(xq[rh * 8 + r][h], w, accq[r]);
    }
#pragma unroll
    for (int r = 0; r < 8; r++) g_q[(q0 + rh * 8 + r) * 128 + c] = accq[r];
}

// ---------------- K3: windowed sparse attention, block per (q, b) -------
__global__ __launch_bounds__(256) void k_attn(const float* __restrict__ x,
                                              const int* gDp, const int* gHp,
                                              const int* gWp, const int* gTp) {
    __shared__ __align__(16) float qs[128];
    __shared__ float ps[2][128];
    __shared__ float dnm[2];
    __shared__ __align__(16) float op[8][128];
    int tid = threadIdx.x;
    int q = blockIdx.x >> 1;
    int b = blockIdx.x & 1;
    if (tid < 128) qs[tid] = g_q[q * 128 + tid];

    // ---- closed-form window: 128 closest integers to u = (a2-N)/(2N) ----
    int gD = *gDp, gH = *gHp, gW = *gWp, gT = *gTp;
    float x0 = x[q * 4 + 0], x1 = x[q * 4 + 1], x2 = x[q * 4 + 2], x3 = x[q * 4 + 3];
    int zi = (int)(x0 * (float)gD);
    int yi = (int)(x1 * (float)gH);
    int xi = (int)(x2 * (float)gW);
    int ti = (int)(x3 * (float)gT);
    int idx = ((ti * gD + zi) * gH + yi) * gW + xi;
    long long Ntot = (long long)gD * gH * gW * gT;
    long long a2 = 2LL * idx * LN;
    long long num = a2 - Ntot, den = 2LL * Ntot;
    long long cl = (num >= 0) ? (num + den - 1) / den : -((-num) / den);  // ceil
    int s = (int)cl - 64;
    if (s < 0) s = 0;
    if (s > LN - TOPK) s = LN - TOPK;
    __syncthreads();

    int lane = tid & 31;
    int warp = tid >> 5;

    // sim: 8 warps x 16 keys; lane owns 4 dims; 16-lane-half reduce = head
    {
        const float* kb = g_kfull + b * LN * 128;
        const float4 q4 = *reinterpret_cast<const float4*>(qs + lane * 4);
#pragma unroll
        for (int kk = 0; kk < 16; kk++) {
            int k = warp * 16 + kk;
            const float4 k4 = *reinterpret_cast<const float4*>(kb + (s + k) * 128 + lane * 4);
            float part = k4.x * q4.x + k4.y * q4.y + k4.z * q4.z + k4.w * q4.w;
            part += __shfl_xor_sync(0xffffffffu, part, 1);
            part += __shfl_xor_sync(0xffffffffu, part, 2);
            part += __shfl_xor_sync(0xffffffffu, part, 4);
            part += __shfl_xor_sync(0xffffffffu, part, 8);
            if ((lane & 15) == 0) ps[lane >> 4][k] = part * 0.125f;
        }
    }
    __syncthreads();
    // softmax (warp 0 -> head 0, warp 1 -> head 1)
    if (tid < 64) {
        int h = warp;
        float v[4];
        float mx = -3.4e38f;
#pragma unroll
        for (int j2 = 0; j2 < 4; j2++) { v[j2] = ps[h][lane + 32 * j2]; mx = fmaxf(mx, v[j2]); }
#pragma unroll
        for (int o2 = 16; o2 > 0; o2 >>= 1) mx = fmaxf(mx, __shfl_xor_sync(0xffffffffu, mx, o2));
        float sum = 0.f;
#pragma unroll
        for (int j2 = 0; j2 < 4; j2++) {
            float ev = expf(v[j2] - mx);
            ps[h][lane + 32 * j2] = ev;
            sum += ev;
        }
#pragma unroll
        for (int o2 = 16; o2 > 0; o2 >>= 1) sum += __shfl_xor_sync(0xffffffffu, sum, o2);
        if (lane == 0) dnm[h] = sum;
    }
    __syncthreads();
    // o: 8 key-groups x (32 lanes x 4 dims), float4 V reads
    {
        int j4 = (tid & 31) * 4;          // dim quad
        int kg = tid >> 5;                // key group: 16 keys
        int h = j4 >> 6;                  // head for these dims
        const float* vb = g_vfull + b * LN * 128;
        float4 acc = make_float4(0.f, 0.f, 0.f, 0.f);
#pragma unroll
        for (int kk = 0; kk < 16; kk++) {
            int k = kg * 16 + kk;
            float p = ps[h][k];
            const float4 v4 = *reinterpret_cast<const float4*>(vb + (s + k) * 128 + j4);
            acc.x = fmaf(p, v4.x, acc.x);
            acc.y = fmaf(p, v4.y, acc.y);
            acc.z = fmaf(p, v4.z, acc.z);
            acc.w = fmaf(p, v4.w, acc.w);
        }
        *reinterpret_cast<float4*>(&op[kg][j4]) = acc;
    }
    __syncthreads();
    if (tid < 128) {
        float v = 0.f;
#pragma unroll
        for (int g = 0; g < 8; g++) v += op[g][tid];
        g_o[((long long)b * QN + q) * 128 + tid] = v / dnm[tid >> 6];
    }
}

// ---------------- K7: out = m0 . outlW0 + hv1 . outlW1 + biases ---------
__global__ __launch_bounds__(256) void k_out(const float* __restrict__ outl_W,
                                             const float* __restrict__ outl_b,
                                             float* __restrict__ out) {
    int tid = threadIdx.x;
    int r = blockIdx.x * 8 + (tid >> 5);
    int lane = tid & 31;
    float acc = 0.f;
#pragma unroll
    for (int j = 0; j < 8; j++) {
        int c = lane + 32 * j;
        acc = fmaf(g_m0[(long long)r * 256 + c],  outl_W[c],       acc);
        acc = fmaf(g_hv1[(long long)r * 256 + c], outl_W[256 + c], acc);
    }
#pragma unroll
    for (int o2 = 16; o2 > 0; o2 >>= 1) acc += __shfl_xor_sync(0xffffffffu, acc, o2);
    if (lane == 0) out[r] = acc + outl_b[0] + outl_b[1];
}

// ---------------- launch ------------------------------------------------
extern "C" void kernel_launch(void* const* d_in, const int* in_sizes, int n_in,
                              void* d_out, int out_size) {
    const float* x       = (const float*)d_in[0];
    const float* tokens  = (const float*)d_in[1];
    const float* query_W = (const float*)d_in[2];
    const float* query_b = (const float*)d_in[3];
    const float* q_W     = (const float*)d_in[4];
    const float* kv_W    = (const float*)d_in[5];
    const float* out_W   = (const float*)d_in[6];
    const float* out_b   = (const float*)d_in[7];
    const float* band_W  = (const float*)d_in[8];
    const float* band_b  = (const float*)d_in[9];
    const float* mod_W   = (const float*)d_in[10];
    const float* mod_b   = (const float*)d_in[11];
    const float* hv_W    = (const float*)d_in[12];
    const float* hv_b    = (const float*)d_in[13];
    const float* outl_W  = (const float*)d_in[14];
    const float* outl_b  = (const float*)d_in[15];
    const int*   gD      = (const int*)d_in[16];
    const int*   gH      = (const int*)d_in[17];
    const int*   gW      = (const int*)d_in[18];
    const int*   gT      = (const int*)d_in[19];
    float* out = (float*)d_out;

    float *kf, *vf, *o, *mod, *m0, *m1, *hv1, *h0, *h1;
    cudaGetSymbolAddress((void**)&kf,  g_kfull);
    cudaGetSymbolAddress((void**)&vf,  g_vfull);
    cudaGetSymbolAddress((void**)&o,   g_o);
    cudaGetSymbolAddress((void**)&mod, g_mod);
    cudaGetSymbolAddress((void**)&m0,  g_m0);
    cudaGetSymbolAddress((void**)&m1,  g_m1);
    cudaGetSymbolAddress((void**)&hv1, g_hv1);
    cudaGetSymbolAddress((void**)&h0,  g_h0);
    cudaGetSymbolAddress((void**)&h1,  g_h1);

    k_gemm<256,0><<<BN*LN/32, 256>>>(tokens, nullptr, kv_W, nullptr, nullptr, kf, vf);
    k_feat<<<QN/16, 256>>>(x, query_W, query_b, q_W, band_W, band_b);
    k_attn<<<BN*QN, 256>>>(x, gD, gH, gW, gT);
    k_gemm<128,1><<<BN*QN/32, 256>>>(o,   nullptr, out_W,             out_b,       nullptr, mod, nullptr);
    k_gemm<256,2><<<BN*QN/32, 256>>>(mod, nullptr, mod_W,             mod_b,       h0,      m0,  nullptr);
    k_gemm<256,2><<<BN*QN/32, 256>>>(mod, nullptr, mod_W + 256 * 256, mod_b + 256, h1,      m1,  nullptr);
    k_gemm<256,3><<<BN*QN/32, 256>>>(m0,  m1,      hv_W,              hv_b,        nullptr, hv1, nullptr);
    k_out<<<BN*QN/8, 256>>>(outl_W, outl_b, out);
}

// round 6
// speedup vs baseline: 2.4970x; 1.0059x over previous
#include <cuda_runtime.h>
#include <cuda_bf16.h>
#include <math.h>

#define QN 4096
#define LN 1024
#define BN 2
#define TOPK 128

// ---------------- scratch (device globals; no allocation) ----------------
__device__ float g_kfull[BN*LN*128];
__device__ __nv_bfloat16 g_vh[BN*LN*128];
__device__ float g_q[QN*128];
__device__ float g_h0[QN*256];
__device__ float g_h1[QN*256];
__device__ float g_o[BN*QN*128];
__device__ float g_mod[BN*QN*256];
__device__ float g_m0[BN*QN*256];
__device__ float g_m1[BN*QN*256];
__device__ float g_hv1[BN*QN*256];

// ---------------- register-blocked GEMM, N=256 split into 2 col-blocks --
// Block: ROWS x 128 cols, 256 threads. Thread: (ROWS/8) rows x 4 cols.
// Inner loop k-vectorized: per 4 k -> RPT LDS.128 + 4 LDG.128 + RPT*16 FFMA.
// MODE 0: kv split -> OUT=k_full (fp32), OUT2=v (bf16), no bias
// MODE 1: OUT = X@W + b
// MODE 2: OUT = relu(hadd[row&4095] + X@W + b)
// MODE 3: OUT = relu((X+X2)@W + b)
template<int KDIM, int ROWS, int MODE>
__global__ __launch_bounds__(256) void k_gemm(const float* __restrict__ X,
                                              const float* __restrict__ X2,
                                              const float* __restrict__ W,
                                              const float* __restrict__ bias,
                                              const float* __restrict__ hadd,
                                              float* __restrict__ OUT,
                                              float* __restrict__ OUT2) {
    __shared__ float a[ROWS][32];
    const int RPT = ROWS / 8;
    int tid = threadIdx.x;
    int cb = blockIdx.x & 1;
    int r0 = (blockIdx.x >> 1) * ROWS;
    int rg = tid >> 5;               // 8 row groups
    int cg = cb * 128 + (tid & 31) * 4;
    float acc[RPT][4];
#pragma unroll
    for (int r = 0; r < RPT; r++)
#pragma unroll
        for (int j = 0; j < 4; j++) acc[r][j] = 0.f;

    for (int kc = 0; kc < KDIM; kc += 32) {
        // stage A chunk [ROWS][32] (float4 per thread)
#pragma unroll
        for (int i = tid; i < ROWS * 8; i += 256) {
            int r = i >> 3, kf = (i & 7) * 4;
            const float* p = X + (long long)(r0 + r) * KDIM + kc + kf;
            float4 v = *reinterpret_cast<const float4*>(p);
            if (MODE == 3) {
                const float* p2 = X2 + (long long)(r0 + r) * KDIM + kc + kf;
                float4 v2 = *reinterpret_cast<const float4*>(p2);
                v.x += v2.x; v.y += v2.y; v.z += v2.z; v.w += v2.w;
            }
            *reinterpret_cast<float4*>(&a[r][kf]) = v;
        }
        __syncthreads();
#pragma unroll
        for (int k0 = 0; k0 < 32; k0 += 4) {
            float av[RPT][4];
#pragma unroll
            for (int r = 0; r < RPT; r++) {
                float4 t = *reinterpret_cast<const float4*>(&a[rg * RPT + r][k0]);
                av[r][0] = t.x; av[r][1] = t.y; av[r][2] = t.z; av[r][3] = t.w;
            }
#pragma unroll
            for (int kk = 0; kk < 4; kk++) {
                const float4 w4 = *reinterpret_cast<const float4*>(
                    W + (long long)(kc + k0 + kk) * 256 + cg);
#pragma unroll
                for (int r = 0; r < RPT; r++) {
                    acc[r][0] = fmaf(av[r][kk], w4.x, acc[r][0]);
                    acc[r][1] = fmaf(av[r][kk], w4.y, acc[r][1]);
                    acc[r][2] = fmaf(av[r][kk], w4.z, acc[r][2]);
                    acc[r][3] = fmaf(av[r][kk], w4.w, acc[r][3]);
                }
            }
        }
        __syncthreads();
    }

    float4 bb = make_float4(0.f, 0.f, 0.f, 0.f);
    if (MODE != 0) bb = *reinterpret_cast<const float4*>(bias + cg);
#pragma unroll
    for (int r = 0; r < RPT; r++) {
        int row = r0 + rg * RPT + r;
        float4 v;
        v.x = acc[r][0] + bb.x; v.y = acc[r][1] + bb.y;
        v.z = acc[r][2] + bb.z; v.w = acc[r][3] + bb.w;
        if (MODE == 2) {
            const float4 h4 = *reinterpret_cast<const float4*>(
                hadd + (long long)(row & (QN - 1)) * 256 + cg);
            v.x += h4.x; v.y += h4.y; v.z += h4.z; v.w += h4.w;
        }
        if (MODE >= 2) {
            v.x = fmaxf(v.x, 0.f); v.y = fmaxf(v.y, 0.f);
            v.z = fmaxf(v.z, 0.f); v.w = fmaxf(v.w, 0.f);
        }
        if (MODE == 0) {
            if (cb == 0) {
                *reinterpret_cast<float4*>(OUT + (long long)row * 128 + cg) = v;
            } else {
                __nv_bfloat16* vp = reinterpret_cast<__nv_bfloat16*>(OUT2)
                                    + (long long)row * 128 + (cg - 128);
                __nv_bfloat162 p0 = __floats2bfloat162_rn(v.x, v.y);
                __nv_bfloat162 p1 = __floats2bfloat162_rn(v.z, v.w);
                uint2 u;
                u.x = *reinterpret_cast<unsigned*>(&p0);
                u.y = *reinterpret_cast<unsigned*>(&p1);
                *reinterpret_cast<uint2*>(vp) = u;
            }
        } else {
            *reinterpret_cast<float4*>(OUT + (long long)row * 256 + cg) = v;
        }
    }
}

// ---------------- K2: gammas, x_q, q, h0, h1 per query ----------------
__global__ __launch_bounds__(256) void k_feat(const float* __restrict__ x,
                                              const float* __restrict__ query_W,
                                              const float* __restrict__ query_b,
                                              const float* __restrict__ q_W,
                                              const float* __restrict__ band_W,
                                              const float* __restrict__ band_b) {
    __shared__ float sg[16][4];
    __shared__ float om0[8], om1[8];
    __shared__ float gq[16][64];
    __shared__ float g1s[16][64];
    __shared__ float xq[16][256];
    int tid = threadIdx.x;
    int q0 = blockIdx.x * 16;                 // 256 blocks
    if (tid < 8) {
        const float stop0 = (float)2.1072099696478683;   // log10(128)
        float e0 = 1.0f + (float)tid * ((stop0 - 1.0f) / 7.0f);
        om0[tid] = (float)exp10((double)e0);
        const float stop1 = (float)1.5051499783199061;   // log10(32)
        float e1 = 1.0f + (float)tid * ((stop1 - 1.0f) / 7.0f);
        om1[tid] = (float)exp10((double)e1);
    }
    if (tid < 64) sg[tid >> 2][tid & 3] = x[(q0 + (tid >> 2)) * 4 + (tid & 3)];
    __syncthreads();
    for (int i = tid; i < 16 * 64; i += 256) {
        int r = i >> 6, f = i & 63;
        int d = f >> 4, j = f & 15;
        float pg = (float)M_PI * sg[r][d];
        int jj = (j < 8) ? j : j - 8;
        float a0 = pg * om0[jj];
        float a1 = pg * om1[jj];
        gq[r][f]  = (j < 8) ? sinf(a0) : cosf(a0);
        g1s[r][f] = (j < 8) ? sinf(a1) : cosf(a1);
    }
    __syncthreads();
    float accx[16], acc0[16], acc1[16];
#pragma unroll
    for (int r = 0; r < 16; r++) { accx[r] = 0.f; acc0[r] = 0.f; acc1[r] = 0.f; }
    for (int f = 0; f < 64; f++) {
        float wq = query_W[f * 256 + tid];
        float w0 = band_W[f * 256 + tid];
        float w1 = band_W[64 * 256 + f * 256 + tid];
#pragma unroll
        for (int r = 0; r < 16; r++) {
            float gv = gq[r][f];
            accx[r] = fmaf(gv, wq, accx[r]);
            acc0[r] = fmaf(gv, w0, acc0[r]);
            acc1[r] = fmaf(g1s[r][f], w1, acc1[r]);
        }
    }
    float qb = query_b[tid], b0 = band_b[tid], b1 = band_b[256 + tid];
#pragma unroll
    for (int r = 0; r < 16; r++) {
        float xv = fmaxf(accx[r] + qb, 0.f);
        xq[r][tid] = xv;
        g_h0[(q0 + r) * 256 + tid] = fmaxf(acc0[r] + b0, 0.f);
        g_h1[(q0 + r) * 256 + tid] = fmaxf(acc1[r] + b1, 0.f);
    }
    __syncthreads();
    int c  = tid & 127;
    int rh = tid >> 7;
    float accq[8];
#pragma unroll
    for (int r = 0; r < 8; r++) accq[r] = 0.f;
    for (int h = 0; h < 256; h++) {
        float w = q_W[h * 128 + c];
#pragma unroll
        for (int r = 0; r < 8; r++) accq[r] = fmaf(xq[rh * 8 + r][h], w, accq[r]);
    }
#pragma unroll
    for (int r = 0; r < 8; r++) g_q[(q0 + rh * 8 + r) * 128 + c] = accq[r];
}

// ---------------- K3: windowed sparse attention, block per (q, b) -------
__global__ __launch_bounds__(256) void k_attn(const float* __restrict__ x,
                                              const int* gDp, const int* gHp,
                                              const int* gWp, const int* gTp) {
    __shared__ __align__(16) float qs[128];
    __shared__ float ps[2][128];
    __shared__ float dnm[2];
    __shared__ __align__(16) float op[8][128];
    int tid = threadIdx.x;
    int q = blockIdx.x >> 1;
    int b = blockIdx.x & 1;
    if (tid < 128) qs[tid] = g_q[q * 128 + tid];

    // ---- closed-form window: 128 closest integers to u = (a2-N)/(2N) ----
    int gD = *gDp, gH = *gHp, gW = *gWp, gT = *gTp;
    float x0 = x[q * 4 + 0], x1 = x[q * 4 + 1], x2 = x[q * 4 + 2], x3 = x[q * 4 + 3];
    int zi = (int)(x0 * (float)gD);
    int yi = (int)(x1 * (float)gH);
    int xi = (int)(x2 * (float)gW);
    int ti = (int)(x3 * (float)gT);
    int idx = ((ti * gD + zi) * gH + yi) * gW + xi;
    long long Ntot = (long long)gD * gH * gW * gT;
    long long a2 = 2LL * idx * LN;
    long long num = a2 - Ntot, den = 2LL * Ntot;
    long long cl = (num >= 0) ? (num + den - 1) / den : -((-num) / den);  // ceil
    int s = (int)cl - 64;
    if (s < 0) s = 0;
    if (s > LN - TOPK) s = LN - TOPK;
    __syncthreads();

    int lane = tid & 31;
    int warp = tid >> 5;

    // sim: 8 warps x 16 keys; lane owns 4 dims (fp32 K)
    {
        const float* kb = g_kfull + b * LN * 128;
        const float4 q4 = *reinterpret_cast<const float4*>(qs + lane * 4);
#pragma unroll
        for (int kk = 0; kk < 16; kk++) {
            int k = warp * 16 + kk;
            const float4 k4 = *reinterpret_cast<const float4*>(kb + (s + k) * 128 + lane * 4);
            float part = k4.x * q4.x + k4.y * q4.y + k4.z * q4.z + k4.w * q4.w;
            part += __shfl_xor_sync(0xffffffffu, part, 1);
            part += __shfl_xor_sync(0xffffffffu, part, 2);
            part += __shfl_xor_sync(0xffffffffu, part, 4);
            part += __shfl_xor_sync(0xffffffffu, part, 8);
            if ((lane & 15) == 0) ps[lane >> 4][k] = part * 0.125f;
        }
    }
    __syncthreads();
    // softmax (warp 0 -> head 0, warp 1 -> head 1)
    if (tid < 64) {
        int h = warp;
        float v[4];
        float mx = -3.4e38f;
#pragma unroll
        for (int j2 = 0; j2 < 4; j2++) { v[j2] = ps[h][lane + 32 * j2]; mx = fmaxf(mx, v[j2]); }
#pragma unroll
        for (int o2 = 16; o2 > 0; o2 >>= 1) mx = fmaxf(mx, __shfl_xor_sync(0xffffffffu, mx, o2));
        float sum = 0.f;
#pragma unroll
        for (int j2 = 0; j2 < 4; j2++) {
            float ev = expf(v[j2] - mx);
            ps[h][lane + 32 * j2] = ev;
            sum += ev;
        }
#pragma unroll
        for (int o2 = 16; o2 > 0; o2 >>= 1) sum += __shfl_xor_sync(0xffffffffu, sum, o2);
        if (lane == 0) dnm[h] = sum;
    }
    __syncthreads();
    // o: 8 key-groups x (32 lanes x 4 dims), bf16 V reads (8B per key)
    {
        int j4 = (tid & 31) * 4;          // dim quad
        int kg = tid >> 5;                // key group: 16 keys
        int h = j4 >> 6;                  // head for these dims
        const __nv_bfloat16* vb = g_vh + b * LN * 128;
        float4 acc = make_float4(0.f, 0.f, 0.f, 0.f);
#pragma unroll
        for (int kk = 0; kk < 16; kk++) {
            int k = kg * 16 + kk;
            float p = ps[h][k];
            uint2 raw = *reinterpret_cast<const uint2*>(vb + (s + k) * 128 + j4);
            __nv_bfloat162 b0 = *reinterpret_cast<__nv_bfloat162*>(&raw.x);
            __nv_bfloat162 b1 = *reinterpret_cast<__nv_bfloat162*>(&raw.y);
            float2 f0 = __bfloat1622float2(b0);
            float2 f1 = __bfloat1622float2(b1);
            acc.x = fmaf(p, f0.x, acc.x);
            acc.y = fmaf(p, f0.y, acc.y);
            acc.z = fmaf(p, f1.x, acc.z);
            acc.w = fmaf(p, f1.y, acc.w);
        }
        *reinterpret_cast<float4*>(&op[kg][j4]) = acc;
    }
    __syncthreads();
    if (tid < 128) {
        float v = 0.f;
#pragma unroll
        for (int g = 0; g < 8; g++) v += op[g][tid];
        g_o[((long long)b * QN + q) * 128 + tid] = v / dnm[tid >> 6];
    }
}

// ---------------- K7: out = m0 . outlW0 + hv1 . outlW1 + biases ---------
__global__ __launch_bounds__(256) void k_out(const float* __restrict__ outl_W,
                                             const float* __restrict__ outl_b,
                                             float* __restrict__ out) {
    int tid = threadIdx.x;
    int r = blockIdx.x * 8 + (tid >> 5);
    int lane = tid & 31;
    float acc = 0.f;
#pragma unroll
    for (int j = 0; j < 8; j++) {
        int c = lane + 32 * j;
        acc = fmaf(g_m0[(long long)r * 256 + c],  outl_W[c],       acc);
        acc = fmaf(g_hv1[(long long)r * 256 + c], outl_W[256 + c], acc);
    }
#pragma unroll
    for (int o2 = 16; o2 > 0; o2 >>= 1) acc += __shfl_xor_sync(0xffffffffu, acc, o2);
    if (lane == 0) out[r] = acc + outl_b[0] + outl_b[1];
}

// ---------------- launch ------------------------------------------------
extern "C" void kernel_launch(void* const* d_in, const int* in_sizes, int n_in,
                              void* d_out, int out_size) {
    const float* x       = (const float*)d_in[0];
    const float* tokens  = (const float*)d_in[1];
    const float* query_W = (const float*)d_in[2];
    const float* query_b = (const float*)d_in[3];
    const float* q_W     = (const float*)d_in[4];
    const float* kv_W    = (const float*)d_in[5];
    const float* out_W   = (const float*)d_in[6];
    const float* out_b   = (const float*)d_in[7];
    const float* band_W  = (const float*)d_in[8];
    const float* band_b  = (const float*)d_in[9];
    const float* mod_W   = (const float*)d_in[10];
    const float* mod_b   = (const float*)d_in[11];
    const float* hv_W    = (const float*)d_in[12];
    const float* hv_b    = (const float*)d_in[13];
    const float* outl_W  = (const float*)d_in[14];
    const float* outl_b  = (const float*)d_in[15];
    const int*   gD      = (const int*)d_in[16];
    const int*   gH      = (const int*)d_in[17];
    const int*   gW      = (const int*)d_in[18];
    const int*   gT      = (const int*)d_in[19];
    float* out = (float*)d_out;

    float *kf, *vf, *o, *mod, *m0, *m1, *hv1, *h0, *h1;
    cudaGetSymbolAddress((void**)&kf,  g_kfull);
    cudaGetSymbolAddress((void**)&vf,  g_vh);
    cudaGetSymbolAddress((void**)&o,   g_o);
    cudaGetSymbolAddress((void**)&mod, g_mod);
    cudaGetSymbolAddress((void**)&m0,  g_m0);
    cudaGetSymbolAddress((void**)&m1,  g_m1);
    cudaGetSymbolAddress((void**)&hv1, g_hv1);
    cudaGetSymbolAddress((void**)&h0,  g_h0);
    cudaGetSymbolAddress((void**)&h1,  g_h1);

    k_gemm<256,32,0><<<(BN*LN/32)*2, 256>>>(tokens, nullptr, kv_W, nullptr, nullptr, kf, vf);
    k_feat<<<QN/16, 256>>>(x, query_W, query_b, q_W, band_W, band_b);
    k_attn<<<BN*QN, 256>>>(x, gD, gH, gW, gT);
    k_gemm<128,64,1><<<(BN*QN/64)*2, 256>>>(o,   nullptr, out_W,             out_b,       nullptr, mod, nullptr);
    k_gemm<256,64,2><<<(BN*QN/64)*2, 256>>>(mod, nullptr, mod_W,             mod_b,       h0,      m0,  nullptr);
    k_gemm<256,64,2><<<(BN*QN/64)*2, 256>>>(mod, nullptr, mod_W + 256 * 256, mod_b + 256, h1,      m1,  nullptr);
    k_gemm<256,64,3><<<(BN*QN/64)*2, 256>>>(m0,  m1,      hv_W,              hv_b,        nullptr, hv1, nullptr);
    k_out<<<BN*QN/8, 256>>>(outl_W, outl_b, out);
}

// round 7
// speedup vs baseline: 2.6426x; 1.0583x over previous
#include <cuda_runtime.h>
#include <cuda_bf16.h>
#include <math.h>

#define QN 4096
#define LN 1024
#define BN 2
#define TOPK 128

// ---------------- scratch (device globals; no allocation) ----------------
__device__ float g_kfull[BN*LN*128];
__device__ __nv_bfloat16 g_vh[BN*LN*128];
__device__ float g_q[QN*128];
__device__ float g_h0[QN*256];
__device__ float g_h1[QN*256];
__device__ float g_o[BN*QN*128];
__device__ float g_mod[BN*QN*256];
__device__ float g_m0[BN*QN*256];
__device__ float g_m1[BN*QN*256];
__device__ float g_hv1[BN*QN*256];

// ------- double-buffered smem GEMM, N=256 split into 2 col-blocks -------
// Block: ROWS x 128 cols, 256 threads. Thread: (ROWS/8) rows x 4 cols.
// Inner loop is pure LDS+FFMA; global loads prefetched one chunk ahead.
// MODE 0: kv split -> OUT=k_full (fp32), OUT2=v (bf16), no bias
// MODE 1: OUT = X@W + b
// MODE 2: OUT = relu(hadd[row&4095] + X@W + b)
// MODE 3: OUT = relu((X+X2)@W + b)
template<int KDIM, int ROWS, int MODE>
__global__ __launch_bounds__(256) void k_gemm(const float* __restrict__ X,
                                              const float* __restrict__ X2,
                                              const float* __restrict__ W,
                                              const float* __restrict__ bias,
                                              const float* __restrict__ hadd,
                                              float* __restrict__ OUT,
                                              float* __restrict__ OUT2) {
    const int RPT = ROWS / 8;            // rows per thread
    const int NCH = KDIM / 16;           // 16-k chunks
    __shared__ float As[2][16][ROWS];    // [k][row] transposed
    __shared__ float Bs[2][16][128];
    int tid = threadIdx.x;
    int cb = blockIdx.x & 1;
    int r0 = (blockIdx.x >> 1) * ROWS;
    int ty = tid >> 5;                   // 8 row groups
    int tx = tid & 31;                   // 32 col groups of 4
    int cg = cb * 128 + tx * 4;

    // A-load assignment: ROWS*4 float4s total
    bool a_act; int a_row, a_kg;
    if (ROWS == 64) { a_act = true;      a_row = tid & 63; a_kg = tid >> 6; }
    else            { a_act = tid < 128; a_row = tid & 31; a_kg = tid >> 5; }
    // B-load assignment: 2048 floats = 8 per thread
    int b_k = tid >> 4, b_c = (tid & 15) * 8;

    float acc[RPT][4];
#pragma unroll
    for (int r = 0; r < RPT; r++)
#pragma unroll
        for (int j = 0; j < 4; j++) acc[r][j] = 0.f;

    // prefetch chunk 0
    float4 apre = make_float4(0.f, 0.f, 0.f, 0.f);
    float4 bpre0, bpre1;
    if (a_act) {
        const float* p = X + (long long)(r0 + a_row) * KDIM + a_kg * 4;
        apre = *reinterpret_cast<const float4*>(p);
        if (MODE == 3) {
            float4 v2 = *reinterpret_cast<const float4*>(
                X2 + (long long)(r0 + a_row) * KDIM + a_kg * 4);
            apre.x += v2.x; apre.y += v2.y; apre.z += v2.z; apre.w += v2.w;
        }
    }
    bpre0 = *reinterpret_cast<const float4*>(W + (long long)b_k * 256 + cg - tx * 4 + b_c);
    bpre1 = *reinterpret_cast<const float4*>(W + (long long)b_k * 256 + cg - tx * 4 + b_c + 4);
    // (cg - tx*4 == cb*128)

    for (int c = 0; c < NCH; c++) {
        int buf = c & 1;
        // store staged regs
        if (a_act) {
            As[buf][a_kg * 4 + 0][a_row] = apre.x;
            As[buf][a_kg * 4 + 1][a_row] = apre.y;
            As[buf][a_kg * 4 + 2][a_row] = apre.z;
            As[buf][a_kg * 4 + 3][a_row] = apre.w;
        }
        *reinterpret_cast<float4*>(&Bs[buf][b_k][b_c])     = bpre0;
        *reinterpret_cast<float4*>(&Bs[buf][b_k][b_c + 4]) = bpre1;
        __syncthreads();
        // prefetch chunk c+1
        if (c + 1 < NCH) {
            int kc = (c + 1) * 16;
            if (a_act) {
                const float* p = X + (long long)(r0 + a_row) * KDIM + kc + a_kg * 4;
                apre = *reinterpret_cast<const float4*>(p);
                if (MODE == 3) {
                    float4 v2 = *reinterpret_cast<const float4*>(
                        X2 + (long long)(r0 + a_row) * KDIM + kc + a_kg * 4);
                    apre.x += v2.x; apre.y += v2.y; apre.z += v2.z; apre.w += v2.w;
                }
            }
            bpre0 = *reinterpret_cast<const float4*>(
                W + (long long)(kc + b_k) * 256 + cb * 128 + b_c);
            bpre1 = *reinterpret_cast<const float4*>(
                W + (long long)(kc + b_k) * 256 + cb * 128 + b_c + 4);
        }
        // compute 16 k-steps from smem
#pragma unroll
        for (int k = 0; k < 16; k++) {
            float4 b4 = *reinterpret_cast<const float4*>(&Bs[buf][k][tx * 4]);
            float ar[RPT];
            if (RPT == 8) {
                float4 t0 = *reinterpret_cast<const float4*>(&As[buf][k][ty * 8]);
                float4 t1 = *reinterpret_cast<const float4*>(&As[buf][k][ty * 8 + 4]);
                ar[0] = t0.x; ar[1] = t0.y; ar[2] = t0.z; ar[3] = t0.w;
                ar[4] = t1.x; ar[5] = t1.y; ar[6] = t1.z; ar[7] = t1.w;
            } else {
                float4 t0 = *reinterpret_cast<const float4*>(&As[buf][k][ty * RPT]);
                ar[0] = t0.x; ar[1] = t0.y; ar[2] = t0.z; ar[3] = t0.w;
            }
#pragma unroll
            for (int r = 0; r < RPT; r++) {
                acc[r][0] = fmaf(ar[r], b4.x, acc[r][0]);
                acc[r][1] = fmaf(ar[r], b4.y, acc[r][1]);
                acc[r][2] = fmaf(ar[r], b4.z, acc[r][2]);
                acc[r][3] = fmaf(ar[r], b4.w, acc[r][3]);
            }
        }
        __syncthreads();
    }

    float4 bb = make_float4(0.f, 0.f, 0.f, 0.f);
    if (MODE != 0) bb = *reinterpret_cast<const float4*>(bias + cg);
#pragma unroll
    for (int r = 0; r < RPT; r++) {
        int row = r0 + ty * RPT + r;
        float4 v;
        v.x = acc[r][0] + bb.x; v.y = acc[r][1] + bb.y;
        v.z = acc[r][2] + bb.z; v.w = acc[r][3] + bb.w;
        if (MODE == 2) {
            const float4 h4 = *reinterpret_cast<const float4*>(
                hadd + (long long)(row & (QN - 1)) * 256 + cg);
            v.x += h4.x; v.y += h4.y; v.z += h4.z; v.w += h4.w;
        }
        if (MODE >= 2) {
            v.x = fmaxf(v.x, 0.f); v.y = fmaxf(v.y, 0.f);
            v.z = fmaxf(v.z, 0.f); v.w = fmaxf(v.w, 0.f);
        }
        if (MODE == 0) {
            if (cb == 0) {
                *reinterpret_cast<float4*>(OUT + (long long)row * 128 + cg) = v;
            } else {
                __nv_bfloat16* vp = reinterpret_cast<__nv_bfloat16*>(OUT2)
                                    + (long long)row * 128 + (cg - 128);
                __nv_bfloat162 p0 = __floats2bfloat162_rn(v.x, v.y);
                __nv_bfloat162 p1 = __floats2bfloat162_rn(v.z, v.w);
                uint2 u;
                u.x = *reinterpret_cast<unsigned*>(&p0);
                u.y = *reinterpret_cast<unsigned*>(&p1);
                *reinterpret_cast<uint2*>(vp) = u;
            }
        } else {
            *reinterpret_cast<float4*>(OUT + (long long)row * 256 + cg) = v;
        }
    }
}

// ---------------- K2: gammas, x_q, q, h0, h1 per query ----------------
__global__ __launch_bounds__(256) void k_feat(const float* __restrict__ x,
                                              const float* __restrict__ query_W,
                                              const float* __restrict__ query_b,
                                              const float* __restrict__ q_W,
                                              const float* __restrict__ band_W,
                                              const float* __restrict__ band_b) {
    __shared__ float sg[16][4];
    __shared__ float om0[8], om1[8];
    __shared__ float gq[16][64];
    __shared__ float g1s[16][64];
    __shared__ float xq[16][256];
    int tid = threadIdx.x;
    int q0 = blockIdx.x * 16;                 // 256 blocks
    if (tid < 8) {
        const float stop0 = (float)2.1072099696478683;   // log10(128)
        float e0 = 1.0f + (float)tid * ((stop0 - 1.0f) / 7.0f);
        om0[tid] = (float)exp10((double)e0);
        const float stop1 = (float)1.5051499783199061;   // log10(32)
        float e1 = 1.0f + (float)tid * ((stop1 - 1.0f) / 7.0f);
        om1[tid] = (float)exp10((double)e1);
    }
    if (tid < 64) sg[tid >> 2][tid & 3] = x[(q0 + (tid >> 2)) * 4 + (tid & 3)];
    __syncthreads();
    for (int i = tid; i < 16 * 64; i += 256) {
        int r = i >> 6, f = i & 63;
        int d = f >> 4, j = f & 15;
        float pg = (float)M_PI * sg[r][d];
        int jj = (j < 8) ? j : j - 8;
        float a0 = pg * om0[jj];
        float a1 = pg * om1[jj];
        gq[r][f]  = (j < 8) ? sinf(a0) : cosf(a0);
        g1s[r][f] = (j < 8) ? sinf(a1) : cosf(a1);
    }
    __syncthreads();
    float accx[16], acc0[16], acc1[16];
#pragma unroll
    for (int r = 0; r < 16; r++) { accx[r] = 0.f; acc0[r] = 0.f; acc1[r] = 0.f; }
    for (int f = 0; f < 64; f++) {
        float wq = query_W[f * 256 + tid];
        float w0 = band_W[f * 256 + tid];
        float w1 = band_W[64 * 256 + f * 256 + tid];
#pragma unroll
        for (int r = 0; r < 16; r++) {
            float gv = gq[r][f];
            accx[r] = fmaf(gv, wq, accx[r]);
            acc0[r] = fmaf(gv, w0, acc0[r]);
            acc1[r] = fmaf(g1s[r][f], w1, acc1[r]);
        }
    }
    float qb = query_b[tid], b0 = band_b[tid], b1 = band_b[256 + tid];
#pragma unroll
    for (int r = 0; r < 16; r++) {
        float xv = fmaxf(accx[r] + qb, 0.f);
        xq[r][tid] = xv;
        g_h0[(q0 + r) * 256 + tid] = fmaxf(acc0[r] + b0, 0.f);
        g_h1[(q0 + r) * 256 + tid] = fmaxf(acc1[r] + b1, 0.f);
    }
    __syncthreads();
    int c  = tid & 127;
    int rh = tid >> 7;
    float accq[8];
#pragma unroll
    for (int r = 0; r < 8; r++) accq[r] = 0.f;
    for (int h = 0; h < 256; h++) {
        float w = q_W[h * 128 + c];
#pragma unroll
        for (int r = 0; r < 8; r++) accq[r] = fmaf(xq[rh * 8 + r][h], w, accq[r]);
    }
#pragma unroll
    for (int r = 0; r < 8; r++) g_q[(q0 + rh * 8 + r) * 128 + c] = accq[r];
}

// ---------------- K3: windowed sparse attention, block per (q, b) -------
__global__ __launch_bounds__(256) void k_attn(const float* __restrict__ x,
                                              const int* gDp, const int* gHp,
                                              const int* gWp, const int* gTp) {
    __shared__ __align__(16) float qs[128];
    __shared__ float ps[2][128];
    __shared__ float dnm[2];
    __shared__ __align__(16) float op[8][128];
    int tid = threadIdx.x;
    int q = blockIdx.x >> 1;
    int b = blockIdx.x & 1;
    if (tid < 128) qs[tid] = g_q[q * 128 + tid];

    // ---- closed-form window: 128 closest integers to u = (a2-N)/(2N) ----
    int gD = *gDp, gH = *gHp, gW = *gWp, gT = *gTp;
    float x0 = x[q * 4 + 0], x1 = x[q * 4 + 1], x2 = x[q * 4 + 2], x3 = x[q * 4 + 3];
    int zi = (int)(x0 * (float)gD);
    int yi = (int)(x1 * (float)gH);
    int xi = (int)(x2 * (float)gW);
    int ti = (int)(x3 * (float)gT);
    int idx = ((ti * gD + zi) * gH + yi) * gW + xi;
    long long Ntot = (long long)gD * gH * gW * gT;
    long long a2 = 2LL * idx * LN;
    long long num = a2 - Ntot, den = 2LL * Ntot;
    long long cl = (num >= 0) ? (num + den - 1) / den : -((-num) / den);  // ceil
    int s = (int)cl - 64;
    if (s < 0) s = 0;
    if (s > LN - TOPK) s = LN - TOPK;
    __syncthreads();

    int lane = tid & 31;
    int warp = tid >> 5;

    // sim: 8 warps x 16 keys; lane owns 4 dims (fp32 K)
    {
        const float* kb = g_kfull + b * LN * 128;
        const float4 q4 = *reinterpret_cast<const float4*>(qs + lane * 4);
#pragma unroll
        for (int kk = 0; kk < 16; kk++) {
            int k = warp * 16 + kk;
            const float4 k4 = *reinterpret_cast<const float4*>(kb + (s + k) * 128 + lane * 4);
            float part = k4.x * q4.x + k4.y * q4.y + k4.z * q4.z + k4.w * q4.w;
            part += __shfl_xor_sync(0xffffffffu, part, 1);
            part += __shfl_xor_sync(0xffffffffu, part, 2);
            part += __shfl_xor_sync(0xffffffffu, part, 4);
            part += __shfl_xor_sync(0xffffffffu, part, 8);
            if ((lane & 15) == 0) ps[lane >> 4][k] = part * 0.125f;
        }
    }
    __syncthreads();
    // softmax (warp 0 -> head 0, warp 1 -> head 1)
    if (tid < 64) {
        int h = warp;
        float v[4];
        float mx = -3.4e38f;
#pragma unroll
        for (int j2 = 0; j2 < 4; j2++) { v[j2] = ps[h][lane + 32 * j2]; mx = fmaxf(mx, v[j2]); }
#pragma unroll
        for (int o2 = 16; o2 > 0; o2 >>= 1) mx = fmaxf(mx, __shfl_xor_sync(0xffffffffu, mx, o2));
        float sum = 0.f;
#pragma unroll
        for (int j2 = 0; j2 < 4; j2++) {
            float ev = expf(v[j2] - mx);
            ps[h][lane + 32 * j2] = ev;
            sum += ev;
        }
#pragma unroll
        for (int o2 = 16; o2 > 0; o2 >>= 1) sum += __shfl_xor_sync(0xffffffffu, sum, o2);
        if (lane == 0) dnm[h] = sum;
    }
    __syncthreads();
    // o: 8 key-groups x (32 lanes x 4 dims), bf16 V reads (8B per key)
    {
        int j4 = (tid & 31) * 4;          // dim quad
        int kg = tid >> 5;                // key group: 16 keys
        int h = j4 >> 6;                  // head for these dims
        const __nv_bfloat16* vb = g_vh + b * LN * 128;
        float4 acc = make_float4(0.f, 0.f, 0.f, 0.f);
#pragma unroll
        for (int kk = 0; kk < 16; kk++) {
            int k = kg * 16 + kk;
            float p = ps[h][k];
            uint2 raw = *reinterpret_cast<const uint2*>(vb + (s + k) * 128 + j4);
            __nv_bfloat162 b0 = *reinterpret_cast<__nv_bfloat162*>(&raw.x);
            __nv_bfloat162 b1 = *reinterpret_cast<__nv_bfloat162*>(&raw.y);
            float2 f0 = __bfloat1622float2(b0);
            float2 f1 = __bfloat1622float2(b1);
            acc.x = fmaf(p, f0.x, acc.x);
            acc.y = fmaf(p, f0.y, acc.y);
            acc.z = fmaf(p, f1.x, acc.z);
            acc.w = fmaf(p, f1.y, acc.w);
        }
        *reinterpret_cast<float4*>(&op[kg][j4]) = acc;
    }
    __syncthreads();
    if (tid < 128) {
        float v = 0.f;
#pragma unroll
        for (int g = 0; g < 8; g++) v += op[g][tid];
        g_o[((long long)b * QN + q) * 128 + tid] = v / dnm[tid >> 6];
    }
}

// ---------------- K7: out = m0 . outlW0 + hv1 . outlW1 + biases ---------
__global__ __launch_bounds__(256) void k_out(const float* __restrict__ outl_W,
                                             const float* __restrict__ outl_b,
                                             float* __restrict__ out) {
    int tid = threadIdx.x;
    int r = blockIdx.x * 8 + (tid >> 5);
    int lane = tid & 31;
    float acc = 0.f;
#pragma unroll
    for (int j = 0; j < 8; j++) {
        int c = lane + 32 * j;
        acc = fmaf(g_m0[(long long)r * 256 + c],  outl_W[c],       acc);
        acc = fmaf(g_hv1[(long long)r * 256 + c], outl_W[256 + c], acc);
    }
#pragma unroll
    for (int o2 = 16; o2 > 0; o2 >>= 1) acc += __shfl_xor_sync(0xffffffffu, acc, o2);
    if (lane == 0) out[r] = acc + outl_b[0] + outl_b[1];
}

// ---------------- launch ------------------------------------------------
extern "C" void kernel_launch(void* const* d_in, const int* in_sizes, int n_in,
                              void* d_out, int out_size) {
    const float* x       = (const float*)d_in[0];
    const float* tokens  = (const float*)d_in[1];
    const float* query_W = (const float*)d_in[2];
    const float* query_b = (const float*)d_in[3];
    const float* q_W     = (const float*)d_in[4];
    const float* kv_W    = (const float*)d_in[5];
    const float* out_W   = (const float*)d_in[6];
    const float* out_b   = (const float*)d_in[7];
    const float* band_W  = (const float*)d_in[8];
    const float* band_b  = (const float*)d_in[9];
    const float* mod_W   = (const float*)d_in[10];
    const float* mod_b   = (const float*)d_in[11];
    const float* hv_W    = (const float*)d_in[12];
    const float* hv_b    = (const float*)d_in[13];
    const float* outl_W  = (const float*)d_in[14];
    const float* outl_b  = (const float*)d_in[15];
    const int*   gD      = (const int*)d_in[16];
    const int*   gH      = (const int*)d_in[17];
    const int*   gW      = (const int*)d_in[18];
    const int*   gT      = (const int*)d_in[19];
    float* out = (float*)d_out;

    float *kf, *vf, *o, *mod, *m0, *m1, *hv1, *h0, *h1;
    cudaGetSymbolAddress((void**)&kf,  g_kfull);
    cudaGetSymbolAddress((void**)&vf,  g_vh);
    cudaGetSymbolAddress((void**)&o,   g_o);
    cudaGetSymbolAddress((void**)&mod, g_mod);
    cudaGetSymbolAddress((void**)&m0,  g_m0);
    cudaGetSymbolAddress((void**)&m1,  g_m1);
    cudaGetSymbolAddress((void**)&hv1, g_hv1);
    cudaGetSymbolAddress((void**)&h0,  g_h0);
    cudaGetSymbolAddress((void**)&h1,  g_h1);

    k_gemm<256,32,0><<<(BN*LN/32)*2, 256>>>(tokens, nullptr, kv_W, nullptr, nullptr, kf, vf);
    k_feat<<<QN/16, 256>>>(x, query_W, query_b, q_W, band_W, band_b);
    k_attn<<<BN*QN, 256>>>(x, gD, gH, gW, gT);
    k_gemm<128,64,1><<<(BN*QN/64)*2, 256>>>(o,   nullptr, out_W,             out_b,       nullptr, mod, nullptr);
    k_gemm<256,64,2><<<(BN*QN/64)*2, 256>>>(mod, nullptr, mod_W,             mod_b,       h0,      m0,  nullptr);
    k_gemm<256,64,2><<<(BN*QN/64)*2, 256>>>(mod, nullptr, mod_W + 256 * 256, mod_b + 256, h1,      m1,  nullptr);
    k_gemm<256,64,3><<<(BN*QN/64)*2, 256>>>(m0,  m1,      hv_W,              hv_b,        nullptr, hv1, nullptr);
    k_out<<<BN*QN/8, 256>>>(outl_W, outl_b, out);
}